// round 8
// baseline (speedup 1.0000x reference)
#include <cuda_runtime.h>
#include <cuda_bf16.h>
#include <cuda_fp16.h>
#include <stdint.h>

// ---------------- scratch (__device__ globals; no allocations) ----------------
__device__ float    g_L[4096 * 128];      // q | k | v | scale rows
__device__ float    g_c[1024 * 128];      // Z_d * exp(M_d - s[n][d])
__device__ float    g_qk[1024 * 1024];
__device__ unsigned g_Menc[1024];         // row max of qk, order-encoded uint
// V^T fp16 pairs, frag-order permuted: g_Bh[k*512 + u(P)], P = m/2 pair index
__device__ uint32_t g_Bh[128 * 512];

__device__ __forceinline__ float ex2(float x) {
    float y; asm("ex2.approx.ftz.f32 %0, %1;" : "=f"(y) : "f"(x)); return y;
}
__device__ __forceinline__ uint32_t smem_u32(const void* p) {
    uint32_t a;
    asm("{ .reg .u64 t; cvta.to.shared.u64 t, %1; cvt.u32.u64 %0, t; }" : "=r"(a) : "l"(p));
    return a;
}
__device__ __forceinline__ uint32_t pack_h2(float a, float b) {
    __half2 h = __floats2half2_rn(a, b);
    return *(uint32_t*)&h;
}
// order-preserving float<->uint (for atomicMax row-max)
__device__ __forceinline__ unsigned enc_f(float f) {
    unsigned u = __float_as_uint(f);
    return (u & 0x80000000u) ? ~u : (u | 0x80000000u);
}
__device__ __forceinline__ float dec_f(unsigned k) {
    return __uint_as_float((k & 0x80000000u) ? (k ^ 0x80000000u) : ~k);
}

// ---- JAX threefry2x32 (partitionable): key=(0,42), ctr=(0,i), out = o0^o1 ----
// Half the rotations go through IMAD.WIDE (fma pipe): rotl(x,r) = lo|hi of
// x * 2^r, and the (lo|hi)^x0 collapses into ONE 3-input LOP3. This moves
// ~10 alu ops/call onto the underused fma pipe at zero net instruction cost.
__device__ __forceinline__ unsigned rot_w(unsigned x, int r) {
    unsigned long long p;
    asm("mul.wide.u32 %0, %1, %2;" : "=l"(p) : "r"(x), "r"(1u << r));
    return (unsigned)p | (unsigned)(p >> 32);
}
__device__ __forceinline__ unsigned tf_bits(unsigned idx) {
    const unsigned K1 = 42u;
    const unsigned K2 = 42u ^ 0x1BD11BDAu;
    unsigned x0, x1;
    x1 = idx + K1;
    x0 = x1;                               // round 1 folded (x0 was 0)
    x1 = rot_w(x1, 13) ^ x0;
#define RW(r) { x0 += x1; x1 = rot_w(x1, (r)) ^ x0; }
#define RS(r) { x0 += x1; x1 = __funnelshift_l(x1, x1, (r)) ^ x0; }
    RS(15) RW(26) RS(6)
    x0 += K1; x1 += K2 + 1u;
    RW(17) RS(29) RW(16) RS(24)
    x0 += K2; x1 += 2u;
    RW(13) RS(15) RW(26) RS(6)
    /* x0 += 0 */ x1 += K1 + 3u;
    RW(17) RS(29) RW(16) RS(24)
    x0 += K1; x1 += K2 + 4u;
    RW(13) RS(15) RW(26) RS(6)
    x0 += K2; x1 += 5u;
#undef RW
#undef RS
    return x0 ^ x1;
}
// keep ⟺ (bits>>9) < 5033165 ⟺ bits < 5033165*512  (uniform<0.6 exact)
__device__ __forceinline__ float keep_or_zero(unsigned idx, float e) {
    return (tf_bits(idx) < 2576980480u) ? e : 0.f;
}

__device__ __forceinline__ void mma16816(float* d,
    uint32_t a0, uint32_t a1, uint32_t a2, uint32_t a3, uint32_t b0, uint32_t b1) {
    asm volatile("mma.sync.aligned.m16n8k16.row.col.f32.f16.f16.f32 "
        "{%0,%1,%2,%3}, {%4,%5,%6,%7}, {%8,%9}, {%0,%1,%2,%3};"
        : "+f"(d[0]), "+f"(d[1]), "+f"(d[2]), "+f"(d[3])
        : "r"(a0), "r"(a1), "r"(a2), "r"(a3), "r"(b0), "r"(b1));
}

#define CP_ASYNC16(dst, src) \
    asm volatile("cp.async.cg.shared.global [%0], [%1], 16;" :: "r"(dst), "l"(src) : "memory")
#define CP_COMMIT() asm volatile("cp.async.commit_group;" ::: "memory")
#define CP_WAIT0()  asm volatile("cp.async.wait_group 0;" ::: "memory")

// ---------------- 1) linear for 4 stacked inputs (direct W read) + M init ----
__global__ void lin_kernel(const float* __restrict__ x1, const float* __restrict__ x2,
                           const float* __restrict__ x3, const float* __restrict__ x4,
                           const float* __restrict__ W, const float* __restrict__ b) {
    __shared__ float xs[8][512];
    int t = threadIdx.x;                 // 128 threads
    int r0 = blockIdx.x * 8;
    if (blockIdx.x < 8) g_Menc[blockIdx.x * 128 + t] = 0u;   // -inf encoding
    const float* srcs[4] = {x1, x2, x3, x4};
#pragma unroll
    for (int i = 0; i < 8; ++i) {
        int fl4 = t + i * 128;
        int r = fl4 >> 7, cg = fl4 & 127;
        int gr = r0 + r;
        const float* src = srcs[gr >> 10];
        *(float4*)&xs[r][cg * 4] = *(const float4*)&src[(gr & 1023) * 512 + cg * 4];
    }
    __syncthreads();
    int j = t;
    float acc[8];
    float bj = b[j];
#pragma unroll
    for (int r = 0; r < 8; ++r) acc[r] = bj;
    const float4* Wr = (const float4*)(W + j * 512);
#pragma unroll 4
    for (int k4 = 0; k4 < 128; ++k4) {
        float4 wv = Wr[k4];
#pragma unroll
        for (int r = 0; r < 8; ++r) {
            acc[r] += xs[r][k4 * 4 + 0] * wv.x;
            acc[r] += xs[r][k4 * 4 + 1] * wv.y;
            acc[r] += xs[r][k4 * 4 + 2] * wv.z;
            acc[r] += xs[r][k4 * 4 + 3] * wv.w;
        }
    }
#pragma unroll
    for (int r = 0; r < 8; ++r) g_L[(r0 + r) * 128 + j] = acc[r];
}

// ---------------- 2) fused: column softmax (blocks 0-127) + vsplit (128-255) -
__global__ void csm_vsplit_kernel() {
    int t = threadIdx.x;                 // 256
    if (blockIdx.x < 128) {
        __shared__ float red[256];
        int d = blockIdx.x;
        const float* S = g_L + 3072 * 128;
        float mx = -1e30f;
        for (int n = t; n < 1024; n += 256) mx = fmaxf(mx, S[n * 128 + d]);
        red[t] = mx; __syncthreads();
        for (int s = 128; s >= 1; s >>= 1) { if (t < s) red[t] = fmaxf(red[t], red[t + s]); __syncthreads(); }
        float Md = red[0]; __syncthreads();
        float z = 0.f;
        for (int n = t; n < 1024; n += 256) z += __expf(S[n * 128 + d] - Md);
        red[t] = z; __syncthreads();
        for (int s = 128; s >= 1; s >>= 1) { if (t < s) red[t] += red[t + s]; __syncthreads(); }
        float Zd = red[0]; __syncthreads();
        for (int n = t; n < 1024; n += 256) g_c[n * 128 + d] = Zd * __expf(Md - S[n * 128 + d]);
    } else {
        __shared__ float tile[32][33];
        const float* V = g_L + 2048 * 128;
        int bid = blockIdx.x - 128;
        int mt = bid & 31, kt = bid >> 5;
#pragma unroll
        for (int i = 0; i < 4; ++i) {
            int fl = t + i * 256;
            int mi = fl >> 5, kj = fl & 31;
            tile[mi][kj] = V[(mt * 32 + mi) * 128 + kt * 32 + kj];
        }
        __syncthreads();
#pragma unroll
        for (int i = 0; i < 2; ++i) {
            int fl = t + i * 256;            // 0..511
            int ki = fl >> 4, mj = fl & 15;
            float v0 = tile[2 * mj][ki], v1 = tile[2 * mj + 1][ki];
            int k = kt * 32 + ki;
            int P = mt * 16 + mj;            // global pair index (m/2)
            int u = (P & ~31) + (P & 16) + ((P & 3) << 2) + ((P >> 2) & 3);
            g_Bh[k * 512 + u] = pack_h2(v0, v1);
        }
    }
}

// ---------------- 3) qk = q @ k^T, fused row-max via atomicMax ---------------
__global__ void qk_kernel() {
    __shared__ float qaT[64][64];
    __shared__ float kbT[64][64];
    const float* q = g_L;
    const float* kmat = g_L + 1024 * 128;
    int t = threadIdx.x;
    int bx = blockIdx.x, by = blockIdx.y;
    int tr = (t >> 4) << 2, tc = (t & 15) << 2;
    float acc[4][4] = {};
    for (int k0 = 0; k0 < 128; k0 += 64) {
        __syncthreads();
#pragma unroll
        for (int i = 0; i < 4; ++i) {
            int fl4 = t + i * 256;
            int r = fl4 >> 4, kg = fl4 & 15;
            float4 va = *(const float4*)&q[(by * 64 + r) * 128 + k0 + kg * 4];
            qaT[kg * 4 + 0][r] = va.x; qaT[kg * 4 + 1][r] = va.y;
            qaT[kg * 4 + 2][r] = va.z; qaT[kg * 4 + 3][r] = va.w;
            float4 vb = *(const float4*)&kmat[(bx * 64 + r) * 128 + k0 + kg * 4];
            kbT[kg * 4 + 0][r] = vb.x; kbT[kg * 4 + 1][r] = vb.y;
            kbT[kg * 4 + 2][r] = vb.z; kbT[kg * 4 + 3][r] = vb.w;
        }
        __syncthreads();
#pragma unroll 8
        for (int kx = 0; kx < 64; ++kx) {
            float a[4], bv[4];
            *(float4*)a  = *(const float4*)&qaT[kx][tr];
            *(float4*)bv = *(const float4*)&kbT[kx][tc];
#pragma unroll
            for (int i = 0; i < 4; ++i)
#pragma unroll
                for (int j = 0; j < 4; ++j) acc[i][j] += a[i] * bv[j];
        }
    }
#pragma unroll
    for (int i = 0; i < 4; ++i) {
        *(float4*)&g_qk[(by * 64 + tr + i) * 1024 + bx * 64 + tc] =
            make_float4(acc[i][0], acc[i][1], acc[i][2], acc[i][3]);
        float m = fmaxf(fmaxf(acc[i][0], acc[i][1]), fmaxf(acc[i][2], acc[i][3]));
        atomicMax(&g_Menc[by * 64 + tr + i], enc_f(m));
    }
}

// ---------------- 4) main: in-register E frags (fp16) x V_hi  (R6 structure) -
// smem: qkrow(4096) | cvals(512) | Vbuf0(24576) | Vbuf1(24576) = 53760B
#define SM_QK   0
#define SM_CV   4096
#define SM_V0   4608
#define SM_V1   (4608 + 24576)
#define SMEM_BYTES (4608 + 2 * 24576)
#define SROW 48   // uint32 row stride (192B): conflict-free LDS.128

__global__ void __launch_bounds__(256, 2)
main_kernel(float* __restrict__ out) {
    extern __shared__ char smem[];
    float* qkrow = (float*)(smem + SM_QK);
    float* cvals = (float*)(smem + SM_CV);
    uint32_t sbase = smem_u32(smem);

    int t = threadIdx.x, w = t >> 5, lane = t & 31;
    int n = blockIdx.x;
    float Mn = dec_f(g_Menc[n]);
    const float4* gBh4 = (const float4*)g_Bh;

    // stage chunk 0 into buf0 via cp.async
    {
#pragma unroll
        for (int i = 0; i < 4; ++i) {
            int fl = t + i * 256;
            int row = fl >> 3, idx = fl & 7;
            CP_ASYNC16(sbase + SM_V0 + (uint32_t)(row * SROW + idx * 4) * 4,
                       gBh4 + row * 128 + idx);
        }
        CP_COMMIT();
    }

    // qk row (pre-subtract Mn) and cvals (pre-mul log2e)
    {
        float4 v = *(const float4*)&g_qk[n * 1024 + t * 4];
        v.x -= Mn; v.y -= Mn; v.z -= Mn; v.w -= Mn;
        *(float4*)&qkrow[t * 4] = v;
        if (t < 128) cvals[t] = g_c[n * 128 + t] * 1.4426950408889634f;
    }
    CP_WAIT0();
    __syncthreads();

    int qa = lane & 3;                 // quad pos -> m pair
    int qr = lane >> 2;                // quad id  -> d row / b col
    int dA = w * 16 + qr, dB = dA + 8;
    float cLA = cvals[dA], cLB = cvals[dB];
    unsigned uA = ((unsigned)n << 17) + ((unsigned)dA << 10);
    unsigned uB = ((unsigned)n << 17) + ((unsigned)dB << 10);

    float acc[16][4];
#pragma unroll
    for (int i = 0; i < 16; ++i)
#pragma unroll
        for (int j = 0; j < 4; ++j) acc[i][j] = 0.f;
    float zA = 0.f, zB = 0.f;

#pragma unroll 1
    for (int c = 0; c < 16; ++c) {
        const uint32_t* VhS = (const uint32_t*)(smem + ((c & 1) ? SM_V1 : SM_V0));

        // prefetch next chunk into other buffer
        if (c < 15) {
            uint32_t dstb = sbase + ((c & 1) ? SM_V0 : SM_V1);
#pragma unroll
            for (int i = 0; i < 4; ++i) {
                int fl = t + i * 256;
                int row = fl >> 3, idx = fl & 7;
                CP_ASYNC16(dstb + (uint32_t)(row * SROW + idx * 4) * 4,
                           gBh4 + row * 128 + (c + 1) * 8 + idx);
            }
            CP_COMMIT();
        }

#pragma unroll 1
        for (int ms2 = 0; ms2 < 2; ++ms2) {
            int m0 = c * 64 + ms2 * 32;
            uint32_t ahi[2][4];
#pragma unroll
            for (int s = 0; s < 2; ++s) {
                int mb = m0 + s * 16 + qa * 2;
                float2 t01 = *(const float2*)&qkrow[mb];
                float2 t89 = *(const float2*)&qkrow[mb + 8];
                float eA0 = ex2(cLA * t01.x), eA1 = ex2(cLA * t01.y);
                float eA8 = ex2(cLA * t89.x), eA9 = ex2(cLA * t89.y);
                float eB0 = ex2(cLB * t01.x), eB1 = ex2(cLB * t01.y);
                float eB8 = ex2(cLB * t89.x), eB9 = ex2(cLB * t89.y);
                zA += (eA0 + eA1) + (eA8 + eA9);
                zB += (eB0 + eB1) + (eB8 + eB9);
                unsigned iA = uA + (unsigned)mb, iB = uB + (unsigned)mb;
                float vA0 = keep_or_zero(iA, eA0),     vA1 = keep_or_zero(iA + 1, eA1);
                float vA8 = keep_or_zero(iA + 8, eA8), vA9 = keep_or_zero(iA + 9, eA9);
                float vB0 = keep_or_zero(iB, eB0),     vB1 = keep_or_zero(iB + 1, eB1);
                float vB8 = keep_or_zero(iB + 8, eB8), vB9 = keep_or_zero(iB + 9, eB9);
                ahi[s][0] = pack_h2(vA0, vA1);
                ahi[s][1] = pack_h2(vB0, vB1);
                ahi[s][2] = pack_h2(vA8, vA9);
                ahi[s][3] = pack_h2(vB8, vB9);
            }
#pragma unroll
            for (int nt = 0; nt < 16; ++nt) {
                int boff = (nt * 8 + qr) * SROW + ms2 * 16 + qa * 4;
                uint4 bh = *(const uint4*)&VhS[boff];
                mma16816(acc[nt], ahi[0][0], ahi[0][1], ahi[0][2], ahi[0][3], bh.x, bh.y);
                mma16816(acc[nt], ahi[1][0], ahi[1][1], ahi[1][2], ahi[1][3], bh.z, bh.w);
            }
        }

        if (c < 15) { CP_WAIT0(); __syncthreads(); }
    }

    // Z quad reduction (lanes 4r..4r+3 share d)
    zA += __shfl_xor_sync(0xffffffffu, zA, 1);
    zA += __shfl_xor_sync(0xffffffffu, zA, 2);
    zB += __shfl_xor_sync(0xffffffffu, zB, 1);
    zB += __shfl_xor_sync(0xffffffffu, zB, 2);
    float izA = 1.0f / (0.6f * zA);
    float izB = 1.0f / (0.6f * zB);

    float* obA = out + ((long)n << 14) + (long)dA * 128 + qa * 2;
    float* obB = out + ((long)n << 14) + (long)dB * 128 + qa * 2;
#pragma unroll
    for (int nt = 0; nt < 16; ++nt) {
        *(float2*)&obA[nt * 8] = make_float2(acc[nt][0] * izA, acc[nt][1] * izA);
        *(float2*)&obB[nt * 8] = make_float2(acc[nt][2] * izB, acc[nt][3] * izB);
    }
}

// ---------------------------------------------------------------------------
extern "C" void kernel_launch(void* const* d_in, const int* in_sizes, int n_in,
                              void* d_out, int out_size) {
    const float* x1 = (const float*)d_in[0];
    const float* x2 = (const float*)d_in[1];
    const float* x3 = (const float*)d_in[2];
    const float* x4 = (const float*)d_in[3];
    const float* W  = (const float*)d_in[4];
    const float* b  = (const float*)d_in[5];
    float* out = (float*)d_out;

    cudaFuncSetAttribute(main_kernel, cudaFuncAttributeMaxDynamicSharedMemorySize, SMEM_BYTES);

    lin_kernel<<<512, 128>>>(x1, x2, x3, x4, W, b);   // launch 1
    csm_vsplit_kernel<<<256, 256>>>();                // launch 2
    qk_kernel<<<dim3(16, 16), 256>>>();               // launch 3
    main_kernel<<<1024, 256, SMEM_BYTES>>>(out);      // launch 4 -> ncu slot
}

// round 9
// speedup vs baseline: 1.0946x; 1.0946x over previous
#include <cuda_runtime.h>
#include <cuda_bf16.h>
#include <cuda_fp16.h>
#include <stdint.h>

// ---------------- scratch (__device__ globals; no allocations) ----------------
__device__ float    g_L[4096 * 128];      // q | k | v | scale rows
__device__ float    g_c[1024 * 128];      // Z_d * exp(M_d - s[n][d])
__device__ float    g_qk[1024 * 1024];
__device__ unsigned g_Menc[1024];         // row max of qk, order-encoded uint
// V^T fp16 pairs, frag-order permuted: g_Bh[k*512 + u(P)], P = m/2 pair index
__device__ uint32_t g_Bh[128 * 512];

__device__ __forceinline__ float ex2(float x) {
    float y; asm("ex2.approx.ftz.f32 %0, %1;" : "=f"(y) : "f"(x)); return y;
}
__device__ __forceinline__ uint32_t smem_u32(const void* p) {
    uint32_t a;
    asm("{ .reg .u64 t; cvta.to.shared.u64 t, %1; cvt.u32.u64 %0, t; }" : "=r"(a) : "l"(p));
    return a;
}
__device__ __forceinline__ uint32_t pack_h2(float a, float b) {
    __half2 h = __floats2half2_rn(a, b);
    return *(uint32_t*)&h;
}
// order-preserving float<->uint (for atomicMax row-max)
__device__ __forceinline__ unsigned enc_f(float f) {
    unsigned u = __float_as_uint(f);
    return (u & 0x80000000u) ? ~u : (u | 0x80000000u);
}
__device__ __forceinline__ float dec_f(unsigned k) {
    return __uint_as_float((k & 0x80000000u) ? (k ^ 0x80000000u) : ~k);
}

// ---- JAX threefry2x32 (partitionable): key=(0,42), ctr=(0,i), out = o0^o1 ----
// (R6 form: funnelshift rotations + plain adds. ptxas already schedules the
//  adds onto IMAD/fma; SHF+LOP3 on alu is the irreducible ~41 ops/elem.)
__device__ __forceinline__ unsigned int jax_threefry_bits(unsigned int idx) {
    const unsigned int K1 = 42u;
    const unsigned int K2 = 42u ^ 0x1BD11BDAu;
    unsigned int x0 = 0u;
    unsigned int x1 = idx + K1;
#define TFR(r) { x0 += x1; x1 = __funnelshift_l(x1, x1, (r)); x1 ^= x0; }
    TFR(13) TFR(15) TFR(26) TFR(6)   x0 += K1; x1 += K2 + 1u;
    TFR(17) TFR(29) TFR(16) TFR(24)  x0 += K2; x1 += 0u + 2u;
    TFR(13) TFR(15) TFR(26) TFR(6)   x0 += 0u; x1 += K1 + 3u;
    TFR(17) TFR(29) TFR(16) TFR(24)  x0 += K1; x1 += K2 + 4u;
    TFR(13) TFR(15) TFR(26) TFR(6)   x0 += K2; x1 += 0u + 5u;
#undef TFR
    return x0 ^ x1;
}
// keep ⟺ (bits>>9) < 5033165 ⟺ bits < 5033165*512  (uniform<0.6 exact)
__device__ __forceinline__ float keep_or_zero(unsigned idx, float e) {
    return (jax_threefry_bits(idx) < 2576980480u) ? e : 0.f;
}

__device__ __forceinline__ void mma16816(float* d,
    uint32_t a0, uint32_t a1, uint32_t a2, uint32_t a3, uint32_t b0, uint32_t b1) {
    asm volatile("mma.sync.aligned.m16n8k16.row.col.f32.f16.f16.f32 "
        "{%0,%1,%2,%3}, {%4,%5,%6,%7}, {%8,%9}, {%0,%1,%2,%3};"
        : "+f"(d[0]), "+f"(d[1]), "+f"(d[2]), "+f"(d[3])
        : "r"(a0), "r"(a1), "r"(a2), "r"(a3), "r"(b0), "r"(b1));
}

#define CP_ASYNC16(dst, src) \
    asm volatile("cp.async.cg.shared.global [%0], [%1], 16;" :: "r"(dst), "l"(src) : "memory")
#define CP_COMMIT() asm volatile("cp.async.commit_group;" ::: "memory")
#define CP_WAIT0()  asm volatile("cp.async.wait_group 0;" ::: "memory")

// ---------------- 1) linear for 4 stacked inputs (direct W read) + M init ----
__global__ void lin_kernel(const float* __restrict__ x1, const float* __restrict__ x2,
                           const float* __restrict__ x3, const float* __restrict__ x4,
                           const float* __restrict__ W, const float* __restrict__ b) {
    __shared__ float xs[8][512];
    int t = threadIdx.x;                 // 128 threads
    int r0 = blockIdx.x * 8;
    if (blockIdx.x < 8) g_Menc[blockIdx.x * 128 + t] = 0u;   // -inf encoding
    const float* srcs[4] = {x1, x2, x3, x4};
#pragma unroll
    for (int i = 0; i < 8; ++i) {
        int fl4 = t + i * 128;
        int r = fl4 >> 7, cg = fl4 & 127;
        int gr = r0 + r;
        const float* src = srcs[gr >> 10];
        *(float4*)&xs[r][cg * 4] = *(const float4*)&src[(gr & 1023) * 512 + cg * 4];
    }
    __syncthreads();
    int j = t;
    float acc[8];
    float bj = b[j];
#pragma unroll
    for (int r = 0; r < 8; ++r) acc[r] = bj;
    const float4* Wr = (const float4*)(W + j * 512);
#pragma unroll 4
    for (int k4 = 0; k4 < 128; ++k4) {
        float4 wv = Wr[k4];
#pragma unroll
        for (int r = 0; r < 8; ++r) {
            acc[r] += xs[r][k4 * 4 + 0] * wv.x;
            acc[r] += xs[r][k4 * 4 + 1] * wv.y;
            acc[r] += xs[r][k4 * 4 + 2] * wv.z;
            acc[r] += xs[r][k4 * 4 + 3] * wv.w;
        }
    }
#pragma unroll
    for (int r = 0; r < 8; ++r) g_L[(r0 + r) * 128 + j] = acc[r];
}

// ---------------- 2) fused mid: qk (0-255) | csm (256-383) | vsplit (384-511) -
__global__ void mid_kernel() {
    __shared__ float sA[64][64];
    __shared__ float sB[64][64];
    int t = threadIdx.x;                 // 256
    int bxAll = blockIdx.x;

    if (bxAll < 256) {
        // ---- qk = q @ k^T tile + fused row-max ----
        const float* q = g_L;
        const float* kmat = g_L + 1024 * 128;
        int bx = bxAll & 15, by = bxAll >> 4;
        int tr = (t >> 4) << 2, tc = (t & 15) << 2;
        float acc[4][4] = {};
        for (int k0 = 0; k0 < 128; k0 += 64) {
            __syncthreads();
#pragma unroll
            for (int i = 0; i < 4; ++i) {
                int fl4 = t + i * 256;
                int r = fl4 >> 4, kg = fl4 & 15;
                float4 va = *(const float4*)&q[(by * 64 + r) * 128 + k0 + kg * 4];
                sA[kg * 4 + 0][r] = va.x; sA[kg * 4 + 1][r] = va.y;
                sA[kg * 4 + 2][r] = va.z; sA[kg * 4 + 3][r] = va.w;
                float4 vb = *(const float4*)&kmat[(bx * 64 + r) * 128 + k0 + kg * 4];
                sB[kg * 4 + 0][r] = vb.x; sB[kg * 4 + 1][r] = vb.y;
                sB[kg * 4 + 2][r] = vb.z; sB[kg * 4 + 3][r] = vb.w;
            }
            __syncthreads();
#pragma unroll 8
            for (int kx = 0; kx < 64; ++kx) {
                float a[4], bv[4];
                *(float4*)a  = *(const float4*)&sA[kx][tr];
                *(float4*)bv = *(const float4*)&sB[kx][tc];
#pragma unroll
                for (int i = 0; i < 4; ++i)
#pragma unroll
                    for (int j = 0; j < 4; ++j) acc[i][j] += a[i] * bv[j];
            }
        }
#pragma unroll
        for (int i = 0; i < 4; ++i) {
            *(float4*)&g_qk[(by * 64 + tr + i) * 1024 + bx * 64 + tc] =
                make_float4(acc[i][0], acc[i][1], acc[i][2], acc[i][3]);
            float m = fmaxf(fmaxf(acc[i][0], acc[i][1]), fmaxf(acc[i][2], acc[i][3]));
            atomicMax(&g_Menc[by * 64 + tr + i], enc_f(m));
        }
    } else if (bxAll < 384) {
        // ---- column softmax -> c ----
        float* red = &sA[0][0];
        int d = bxAll - 256;
        const float* S = g_L + 3072 * 128;
        float mx = -1e30f;
        for (int n = t; n < 1024; n += 256) mx = fmaxf(mx, S[n * 128 + d]);
        red[t] = mx; __syncthreads();
        for (int s = 128; s >= 1; s >>= 1) { if (t < s) red[t] = fmaxf(red[t], red[t + s]); __syncthreads(); }
        float Md = red[0]; __syncthreads();
        float z = 0.f;
        for (int n = t; n < 1024; n += 256) z += __expf(S[n * 128 + d] - Md);
        red[t] = z; __syncthreads();
        for (int s = 128; s >= 1; s >>= 1) { if (t < s) red[t] += red[t + s]; __syncthreads(); }
        float Zd = red[0]; __syncthreads();
        for (int n = t; n < 1024; n += 256) g_c[n * 128 + d] = Zd * __expf(Md - S[n * 128 + d]);
    } else {
        // ---- V transpose + fp16 pack, frag-order permute ----
        float (*tile)[64] = sA;          // uses 32 rows x <=33 cols of sA
        const float* V = g_L + 2048 * 128;
        int bid = bxAll - 384;
        int mt = bid & 31, kt = bid >> 5;
#pragma unroll
        for (int i = 0; i < 4; ++i) {
            int fl = t + i * 256;
            int mi = fl >> 5, kj = fl & 31;
            tile[mi][kj] = V[(mt * 32 + mi) * 128 + kt * 32 + kj];
        }
        __syncthreads();
#pragma unroll
        for (int i = 0; i < 2; ++i) {
            int fl = t + i * 256;            // 0..511
            int ki = fl >> 4, mj = fl & 15;
            float v0 = tile[2 * mj][ki], v1 = tile[2 * mj + 1][ki];
            int k = kt * 32 + ki;
            int P = mt * 16 + mj;            // global pair index (m/2)
            int u = (P & ~31) + (P & 16) + ((P & 3) << 2) + ((P >> 2) & 3);
            g_Bh[k * 512 + u] = pack_h2(v0, v1);
        }
    }
}

// ---------------- 3) main: in-register E frags (fp16) x V_hi  (R6 exact) -----
// smem: qkrow(4096) | cvals(512) | Vbuf0(24576) | Vbuf1(24576) = 53760B
#define SM_QK   0
#define SM_CV   4096
#define SM_V0   4608
#define SM_V1   (4608 + 24576)
#define SMEM_BYTES (4608 + 2 * 24576)
#define SROW 48   // uint32 row stride (192B): conflict-free LDS.128

__global__ void __launch_bounds__(256, 2)
main_kernel(float* __restrict__ out) {
    extern __shared__ char smem[];
    float* qkrow = (float*)(smem + SM_QK);
    float* cvals = (float*)(smem + SM_CV);
    uint32_t sbase = smem_u32(smem);

    int t = threadIdx.x, w = t >> 5, lane = t & 31;
    int n = blockIdx.x;
    float Mn = dec_f(g_Menc[n]);
    const float4* gBh4 = (const float4*)g_Bh;

    // stage chunk 0 into buf0 via cp.async
    {
#pragma unroll
        for (int i = 0; i < 4; ++i) {
            int fl = t + i * 256;
            int row = fl >> 3, idx = fl & 7;
            CP_ASYNC16(sbase + SM_V0 + (uint32_t)(row * SROW + idx * 4) * 4,
                       gBh4 + row * 128 + idx);
        }
        CP_COMMIT();
    }

    // qk row (pre-subtract Mn) and cvals (pre-mul log2e)
    {
        float4 v = *(const float4*)&g_qk[n * 1024 + t * 4];
        v.x -= Mn; v.y -= Mn; v.z -= Mn; v.w -= Mn;
        *(float4*)&qkrow[t * 4] = v;
        if (t < 128) cvals[t] = g_c[n * 128 + t] * 1.4426950408889634f;
    }
    CP_WAIT0();
    __syncthreads();

    int qa = lane & 3;                 // quad pos -> m pair
    int qr = lane >> 2;                // quad id  -> d row / b col
    int dA = w * 16 + qr, dB = dA + 8;
    float cLA = cvals[dA], cLB = cvals[dB];
    unsigned uA = ((unsigned)n << 17) + ((unsigned)dA << 10);
    unsigned uB = ((unsigned)n << 17) + ((unsigned)dB << 10);

    float acc[16][4];
#pragma unroll
    for (int i = 0; i < 16; ++i)
#pragma unroll
        for (int j = 0; j < 4; ++j) acc[i][j] = 0.f;
    float zA = 0.f, zB = 0.f;

#pragma unroll 1
    for (int c = 0; c < 16; ++c) {
        const uint32_t* VhS = (const uint32_t*)(smem + ((c & 1) ? SM_V1 : SM_V0));

        // prefetch next chunk into other buffer
        if (c < 15) {
            uint32_t dstb = sbase + ((c & 1) ? SM_V0 : SM_V1);
#pragma unroll
            for (int i = 0; i < 4; ++i) {
                int fl = t + i * 256;
                int row = fl >> 3, idx = fl & 7;
                CP_ASYNC16(dstb + (uint32_t)(row * SROW + idx * 4) * 4,
                           gBh4 + row * 128 + (c + 1) * 8 + idx);
            }
            CP_COMMIT();
        }

#pragma unroll 1
        for (int ms2 = 0; ms2 < 2; ++ms2) {
            int m0 = c * 64 + ms2 * 32;
            uint32_t ahi[2][4];
#pragma unroll
            for (int s = 0; s < 2; ++s) {
                int mb = m0 + s * 16 + qa * 2;
                float2 t01 = *(const float2*)&qkrow[mb];
                float2 t89 = *(const float2*)&qkrow[mb + 8];
                float eA0 = ex2(cLA * t01.x), eA1 = ex2(cLA * t01.y);
                float eA8 = ex2(cLA * t89.x), eA9 = ex2(cLA * t89.y);
                float eB0 = ex2(cLB * t01.x), eB1 = ex2(cLB * t01.y);
                float eB8 = ex2(cLB * t89.x), eB9 = ex2(cLB * t89.y);
                zA += (eA0 + eA1) + (eA8 + eA9);
                zB += (eB0 + eB1) + (eB8 + eB9);
                unsigned iA = uA + (unsigned)mb, iB = uB + (unsigned)mb;
                float vA0 = keep_or_zero(iA, eA0),     vA1 = keep_or_zero(iA + 1, eA1);
                float vA8 = keep_or_zero(iA + 8, eA8), vA9 = keep_or_zero(iA + 9, eA9);
                float vB0 = keep_or_zero(iB, eB0),     vB1 = keep_or_zero(iB + 1, eB1);
                float vB8 = keep_or_zero(iB + 8, eB8), vB9 = keep_or_zero(iB + 9, eB9);
                ahi[s][0] = pack_h2(vA0, vA1);
                ahi[s][1] = pack_h2(vB0, vB1);
                ahi[s][2] = pack_h2(vA8, vA9);
                ahi[s][3] = pack_h2(vB8, vB9);
            }
#pragma unroll
            for (int nt = 0; nt < 16; ++nt) {
                int boff = (nt * 8 + qr) * SROW + ms2 * 16 + qa * 4;
                uint4 bh = *(const uint4*)&VhS[boff];
                mma16816(acc[nt], ahi[0][0], ahi[0][1], ahi[0][2], ahi[0][3], bh.x, bh.y);
                mma16816(acc[nt], ahi[1][0], ahi[1][1], ahi[1][2], ahi[1][3], bh.z, bh.w);
            }
        }

        if (c < 15) { CP_WAIT0(); __syncthreads(); }
    }

    // Z quad reduction (lanes 4r..4r+3 share d)
    zA += __shfl_xor_sync(0xffffffffu, zA, 1);
    zA += __shfl_xor_sync(0xffffffffu, zA, 2);
    zB += __shfl_xor_sync(0xffffffffu, zB, 1);
    zB += __shfl_xor_sync(0xffffffffu, zB, 2);
    float izA = 1.0f / (0.6f * zA);
    float izB = 1.0f / (0.6f * zB);

    float* obA = out + ((long)n << 14) + (long)dA * 128 + qa * 2;
    float* obB = out + ((long)n << 14) + (long)dB * 128 + qa * 2;
#pragma unroll
    for (int nt = 0; nt < 16; ++nt) {
        *(float2*)&obA[nt * 8] = make_float2(acc[nt][0] * izA, acc[nt][1] * izA);
        *(float2*)&obB[nt * 8] = make_float2(acc[nt][2] * izB, acc[nt][3] * izB);
    }
}

// ---------------------------------------------------------------------------
extern "C" void kernel_launch(void* const* d_in, const int* in_sizes, int n_in,
                              void* d_out, int out_size) {
    const float* x1 = (const float*)d_in[0];
    const float* x2 = (const float*)d_in[1];
    const float* x3 = (const float*)d_in[2];
    const float* x4 = (const float*)d_in[3];
    const float* W  = (const float*)d_in[4];
    const float* b  = (const float*)d_in[5];
    float* out = (float*)d_out;

    cudaFuncSetAttribute(main_kernel, cudaFuncAttributeMaxDynamicSharedMemorySize, SMEM_BYTES);

    lin_kernel<<<512, 128>>>(x1, x2, x3, x4, W, b);   // launch 1
    mid_kernel<<<512, 256>>>();                       // launch 2: qk|csm|vsplit
    main_kernel<<<1024, 256, SMEM_BYTES>>>(out);      // launch 3
}

// round 11
// speedup vs baseline: 1.1380x; 1.0396x over previous
#include <cuda_runtime.h>
#include <cuda_bf16.h>
#include <cuda_fp16.h>
#include <stdint.h>

// ---------------- scratch (__device__ globals; no allocations) ----------------
__device__ float    g_L[4096 * 128];      // q | k | v | scale rows
__device__ float    g_c[1024 * 128];      // Z_d * exp(M_d - s[n][d])
__device__ float    g_qk[1024 * 1024];
__device__ unsigned g_Menc[1024];         // row max of qk, order-encoded uint
// V^T fp16 pairs, frag-order permuted: g_Bh[k*512 + u(P)], P = m/2 pair index
__device__ uint32_t g_Bh[128 * 512];

__device__ __forceinline__ float ex2(float x) {
    float y; asm("ex2.approx.ftz.f32 %0, %1;" : "=f"(y) : "f"(x)); return y;
}
__device__ __forceinline__ uint32_t smem_u32(const void* p) {
    uint32_t a;
    asm("{ .reg .u64 t; cvta.to.shared.u64 t, %1; cvt.u32.u64 %0, t; }" : "=r"(a) : "l"(p));
    return a;
}
__device__ __forceinline__ uint32_t pack_h2(float a, float b) {
    __half2 h = __floats2half2_rn(a, b);
    return *(uint32_t*)&h;
}
__device__ __forceinline__ float2 h2f2(uint32_t u) {
    __half2 h = *(__half2*)&u;
    return __half22float2(h);
}
// order-preserving float<->uint (for atomicMax row-max)
__device__ __forceinline__ unsigned enc_f(float f) {
    unsigned u = __float_as_uint(f);
    return (u & 0x80000000u) ? ~u : (u | 0x80000000u);
}
__device__ __forceinline__ float dec_f(unsigned k) {
    return __uint_as_float((k & 0x80000000u) ? (k ^ 0x80000000u) : ~k);
}

// ---- JAX threefry2x32 (partitionable): key=(0,42), ctr=(0,i), out = o0^o1 ----
__device__ __forceinline__ unsigned int jax_threefry_bits(unsigned int idx) {
    const unsigned int K1 = 42u;
    const unsigned int K2 = 42u ^ 0x1BD11BDAu;
    unsigned int x0 = 0u;
    unsigned int x1 = idx + K1;
#define TFR(r) { x0 += x1; x1 = __funnelshift_l(x1, x1, (r)); x1 ^= x0; }
    TFR(13) TFR(15) TFR(26) TFR(6)   x0 += K1; x1 += K2 + 1u;
    TFR(17) TFR(29) TFR(16) TFR(24)  x0 += K2; x1 += 0u + 2u;
    TFR(13) TFR(15) TFR(26) TFR(6)   x0 += 0u; x1 += K1 + 3u;
    TFR(17) TFR(29) TFR(16) TFR(24)  x0 += K1; x1 += K2 + 4u;
    TFR(13) TFR(15) TFR(26) TFR(6)   x0 += K2; x1 += 0u + 5u;
#undef TFR
    return x0 ^ x1;
}
// keep ⟺ (bits>>9) < 5033165 ⟺ bits < 5033165*512  (uniform<0.6 exact)
__device__ __forceinline__ float keep_or_zero(unsigned idx, float e) {
    return (jax_threefry_bits(idx) < 2576980480u) ? e : 0.f;
}

__device__ __forceinline__ void mma16816(float* d,
    uint32_t a0, uint32_t a1, uint32_t a2, uint32_t a3, uint32_t b0, uint32_t b1) {
    asm volatile("mma.sync.aligned.m16n8k16.row.col.f32.f16.f16.f32 "
        "{%0,%1,%2,%3}, {%4,%5,%6,%7}, {%8,%9}, {%0,%1,%2,%3};"
        : "+f"(d[0]), "+f"(d[1]), "+f"(d[2]), "+f"(d[3])
        : "r"(a0), "r"(a1), "r"(a2), "r"(a3), "r"(b0), "r"(b1));
}

#define CP_ASYNC16(dst, src) \
    asm volatile("cp.async.cg.shared.global [%0], [%1], 16;" :: "r"(dst), "l"(src) : "memory")
#define CP_COMMIT() asm volatile("cp.async.commit_group;" ::: "memory")
#define CP_WAIT0()  asm volatile("cp.async.wait_group 0;" ::: "memory")

// ---------------- 1) lin via tensor cores, exact hi/lo split -----------------
// C[4096,128] = X @ W^T + b.  Block: 64 rows x 128 j, 8 k-chunks of 64.
// Layout (uint32 words): Xh[64 rows] | Xl[64] | Wh[128] | Wl[128], LROW each.
#define LROW 36
#define LIN_SMEM (384 * LROW * 4)   // 55296 bytes

__global__ void __launch_bounds__(256)
lin_kernel(const float* __restrict__ x1, const float* __restrict__ x2,
           const float* __restrict__ x3, const float* __restrict__ x4,
           const float* __restrict__ W, const float* __restrict__ b) {
    extern __shared__ uint32_t lsm[];
    uint32_t* Xh = lsm;
    uint32_t* Xl = lsm + 64 * LROW;
    uint32_t* Wh = lsm + 128 * LROW;
    uint32_t* Wl = lsm + 256 * LROW;     // FIX: was 192*LROW (overlapped Wh)

    int t = threadIdx.x, w = t >> 5, lane = t & 31;
    int rb = blockIdx.x;                 // 64 blocks
    int r0 = rb * 64;
    if (t < 16) g_Menc[rb * 16 + t] = 0u;   // -inf encoding (1024 over 64 blocks)

    const float* srcs[4] = {x1, x2, x3, x4};
    const float* xsrc = srcs[rb >> 4];
    int rloc = (r0 & 1023);

    int qa = lane & 3, qr = lane >> 2;
    int rt0 = (w & 3) << 4;              // 16-row tile
    int jh  = (w >> 2) << 6;             // 64-col half
    float acc[8][4];
#pragma unroll
    for (int i = 0; i < 8; ++i)
#pragma unroll
        for (int j = 0; j < 4; ++j) acc[i][j] = 0.f;

#pragma unroll 1
    for (int c = 0; c < 8; ++c) {
        __syncthreads();
        // stage X chunk 64x64 -> hi/lo pairs
#pragma unroll
        for (int i = 0; i < 4; ++i) {
            int fl = t + i * 256;            // 0..1023
            int row = fl >> 4, f4 = fl & 15;
            float4 v = *(const float4*)&xsrc[(rloc + row) * 512 + c * 64 + f4 * 4];
            uint32_t h0 = pack_h2(v.x, v.y), h1 = pack_h2(v.z, v.w);
            float2 f0 = h2f2(h0), f1 = h2f2(h1);
            int o = row * LROW + f4 * 2;
            Xh[o] = h0; Xh[o + 1] = h1;
            Xl[o]     = pack_h2(v.x - f0.x, v.y - f0.y);
            Xl[o + 1] = pack_h2(v.z - f1.x, v.w - f1.y);
        }
        // stage W chunk 128x64 -> hi/lo pairs
#pragma unroll
        for (int i = 0; i < 8; ++i) {
            int fl = t + i * 256;            // 0..2047
            int j = fl >> 4, f4 = fl & 15;
            float4 v = *(const float4*)&W[j * 512 + c * 64 + f4 * 4];
            uint32_t h0 = pack_h2(v.x, v.y), h1 = pack_h2(v.z, v.w);
            float2 f0 = h2f2(h0), f1 = h2f2(h1);
            int o = j * LROW + f4 * 2;
            Wh[o] = h0; Wh[o + 1] = h1;
            Wl[o]     = pack_h2(v.x - f0.x, v.y - f0.y);
            Wl[o + 1] = pack_h2(v.z - f1.x, v.w - f1.y);
        }
        __syncthreads();

#pragma unroll
        for (int ks = 0; ks < 4; ++ks) {
            int kp = ks * 8 + qa;
            int ra = (rt0 + qr) * LROW, rb8 = (rt0 + qr + 8) * LROW;
            uint32_t ah0 = Xh[ra + kp],     ah1 = Xh[rb8 + kp];
            uint32_t ah2 = Xh[ra + kp + 4], ah3 = Xh[rb8 + kp + 4];
            uint32_t al0 = Xl[ra + kp],     al1 = Xl[rb8 + kp];
            uint32_t al2 = Xl[ra + kp + 4], al3 = Xl[rb8 + kp + 4];
#pragma unroll
            for (int jt = 0; jt < 8; ++jt) {
                int jr = (jh + jt * 8 + qr) * LROW;
                uint32_t bh0 = Wh[jr + kp], bh1 = Wh[jr + kp + 4];
                uint32_t bl0 = Wl[jr + kp], bl1 = Wl[jr + kp + 4];
                mma16816(acc[jt], ah0, ah1, ah2, ah3, bh0, bh1);
                mma16816(acc[jt], ah0, ah1, ah2, ah3, bl0, bl1);
                mma16816(acc[jt], al0, al1, al2, al3, bh0, bh1);
            }
        }
    }

    // epilogue: + bias, write g_L
    int row0 = r0 + rt0 + qr;
#pragma unroll
    for (int jt = 0; jt < 8; ++jt) {
        int col = jh + jt * 8 + qa * 2;
        float2 bb = *(const float2*)&b[col];
        *(float2*)&g_L[row0 * 128 + col] =
            make_float2(acc[jt][0] + bb.x, acc[jt][1] + bb.y);
        *(float2*)&g_L[(row0 + 8) * 128 + col] =
            make_float2(acc[jt][2] + bb.x, acc[jt][3] + bb.y);
    }
}

// ---------------- 2) fused mid: qk (0-255) | csm (256-383) | vsplit (384-511) -
__global__ void mid_kernel() {
    __shared__ float sA[64][64];
    __shared__ float sB[64][64];
    int t = threadIdx.x;                 // 256
    int bxAll = blockIdx.x;

    if (bxAll < 256) {
        // ---- qk = q @ k^T tile + fused row-max ----
        const float* q = g_L;
        const float* kmat = g_L + 1024 * 128;
        int bx = bxAll & 15, by = bxAll >> 4;
        int tr = (t >> 4) << 2, tc = (t & 15) << 2;
        float acc[4][4] = {};
        for (int k0 = 0; k0 < 128; k0 += 64) {
            __syncthreads();
#pragma unroll
            for (int i = 0; i < 4; ++i) {
                int fl4 = t + i * 256;
                int r = fl4 >> 4, kg = fl4 & 15;
                float4 va = *(const float4*)&q[(by * 64 + r) * 128 + k0 + kg * 4];
                sA[kg * 4 + 0][r] = va.x; sA[kg * 4 + 1][r] = va.y;
                sA[kg * 4 + 2][r] = va.z; sA[kg * 4 + 3][r] = va.w;
                float4 vb = *(const float4*)&kmat[(bx * 64 + r) * 128 + k0 + kg * 4];
                sB[kg * 4 + 0][r] = vb.x; sB[kg * 4 + 1][r] = vb.y;
                sB[kg * 4 + 2][r] = vb.z; sB[kg * 4 + 3][r] = vb.w;
            }
            __syncthreads();
#pragma unroll 8
            for (int kx = 0; kx < 64; ++kx) {
                float a[4], bv[4];
                *(float4*)a  = *(const float4*)&sA[kx][tr];
                *(float4*)bv = *(const float4*)&sB[kx][tc];
#pragma unroll
                for (int i = 0; i < 4; ++i)
#pragma unroll
                    for (int j = 0; j < 4; ++j) acc[i][j] += a[i] * bv[j];
            }
        }
#pragma unroll
        for (int i = 0; i < 4; ++i) {
            *(float4*)&g_qk[(by * 64 + tr + i) * 1024 + bx * 64 + tc] =
                make_float4(acc[i][0], acc[i][1], acc[i][2], acc[i][3]);
            float m = fmaxf(fmaxf(acc[i][0], acc[i][1]), fmaxf(acc[i][2], acc[i][3]));
            atomicMax(&g_Menc[by * 64 + tr + i], enc_f(m));
        }
    } else if (bxAll < 384) {
        // ---- column softmax -> c ----
        float* red = &sA[0][0];
        int d = bxAll - 256;
        const float* S = g_L + 3072 * 128;
        float mx = -1e30f;
        for (int n = t; n < 1024; n += 256) mx = fmaxf(mx, S[n * 128 + d]);
        red[t] = mx; __syncthreads();
        for (int s = 128; s >= 1; s >>= 1) { if (t < s) red[t] = fmaxf(red[t], red[t + s]); __syncthreads(); }
        float Md = red[0]; __syncthreads();
        float z = 0.f;
        for (int n = t; n < 1024; n += 256) z += __expf(S[n * 128 + d] - Md);
        red[t] = z; __syncthreads();
        for (int s = 128; s >= 1; s >>= 1) { if (t < s) red[t] += red[t + s]; __syncthreads(); }
        float Zd = red[0]; __syncthreads();
        for (int n = t; n < 1024; n += 256) g_c[n * 128 + d] = Zd * __expf(Md - S[n * 128 + d]);
    } else {
        // ---- V transpose + fp16 pack, frag-order permute ----
        float (*tile)[64] = sA;
        const float* V = g_L + 2048 * 128;
        int bid = bxAll - 384;
        int mt = bid & 31, kt = bid >> 5;
#pragma unroll
        for (int i = 0; i < 4; ++i) {
            int fl = t + i * 256;
            int mi = fl >> 5, kj = fl & 31;
            tile[mi][kj] = V[(mt * 32 + mi) * 128 + kt * 32 + kj];
        }
        __syncthreads();
#pragma unroll
        for (int i = 0; i < 2; ++i) {
            int fl = t + i * 256;            // 0..511
            int ki = fl >> 4, mj = fl & 15;
            float v0 = tile[2 * mj][ki], v1 = tile[2 * mj + 1][ki];
            int k = kt * 32 + ki;
            int P = mt * 16 + mj;            // global pair index (m/2)
            int u = (P & ~31) + (P & 16) + ((P & 3) << 2) + ((P >> 2) & 3);
            g_Bh[k * 512 + u] = pack_h2(v0, v1);
        }
    }
}

// ---------------- 3) main: in-register E frags (fp16) x V_hi  (R6 exact) -----
// smem: qkrow(4096) | cvals(512) | Vbuf0(24576) | Vbuf1(24576) = 53760B
#define SM_QK   0
#define SM_CV   4096
#define SM_V0   4608
#define SM_V1   (4608 + 24576)
#define SMEM_BYTES (4608 + 2 * 24576)
#define SROW 48   // uint32 row stride (192B): conflict-free LDS.128

__global__ void __launch_bounds__(256, 2)
main_kernel(float* __restrict__ out) {
    extern __shared__ char smem[];
    float* qkrow = (float*)(smem + SM_QK);
    float* cvals = (float*)(smem + SM_CV);
    uint32_t sbase = smem_u32(smem);

    int t = threadIdx.x, w = t >> 5, lane = t & 31;
    int n = blockIdx.x;
    float Mn = dec_f(g_Menc[n]);
    const float4* gBh4 = (const float4*)g_Bh;

    // stage chunk 0 into buf0 via cp.async
    {
#pragma unroll
        for (int i = 0; i < 4; ++i) {
            int fl = t + i * 256;
            int row = fl >> 3, idx = fl & 7;
            CP_ASYNC16(sbase + SM_V0 + (uint32_t)(row * SROW + idx * 4) * 4,
                       gBh4 + row * 128 + idx);
        }
        CP_COMMIT();
    }

    // qk row (pre-subtract Mn) and cvals (pre-mul log2e)
    {
        float4 v = *(const float4*)&g_qk[n * 1024 + t * 4];
        v.x -= Mn; v.y -= Mn; v.z -= Mn; v.w -= Mn;
        *(float4*)&qkrow[t * 4] = v;
        if (t < 128) cvals[t] = g_c[n * 128 + t] * 1.4426950408889634f;
    }
    CP_WAIT0();
    __syncthreads();

    int qa = lane & 3;                 // quad pos -> m pair
    int qr = lane >> 2;                // quad id  -> d row / b col
    int dA = w * 16 + qr, dB = dA + 8;
    float cLA = cvals[dA], cLB = cvals[dB];
    unsigned uA = ((unsigned)n << 17) + ((unsigned)dA << 10);
    unsigned uB = ((unsigned)n << 17) + ((unsigned)dB << 10);

    float acc[16][4];
#pragma unroll
    for (int i = 0; i < 16; ++i)
#pragma unroll
        for (int j = 0; j < 4; ++j) acc[i][j] = 0.f;
    float zA = 0.f, zB = 0.f;

#pragma unroll 1
    for (int c = 0; c < 16; ++c) {
        const uint32_t* VhS = (const uint32_t*)(smem + ((c & 1) ? SM_V1 : SM_V0));

        // prefetch next chunk into other buffer
        if (c < 15) {
            uint32_t dstb = sbase + ((c & 1) ? SM_V0 : SM_V1);
#pragma unroll
            for (int i = 0; i < 4; ++i) {
                int fl = t + i * 256;
                int row = fl >> 3, idx = fl & 7;
                CP_ASYNC16(dstb + (uint32_t)(row * SROW + idx * 4) * 4,
                           gBh4 + row * 128 + (c + 1) * 8 + idx);
            }
            CP_COMMIT();
        }

#pragma unroll 1
        for (int ms2 = 0; ms2 < 2; ++ms2) {
            int m0 = c * 64 + ms2 * 32;
            uint32_t ahi[2][4];
#pragma unroll
            for (int s = 0; s < 2; ++s) {
                int mb = m0 + s * 16 + qa * 2;
                float2 t01 = *(const float2*)&qkrow[mb];
                float2 t89 = *(const float2*)&qkrow[mb + 8];
                float eA0 = ex2(cLA * t01.x), eA1 = ex2(cLA * t01.y);
                float eA8 = ex2(cLA * t89.x), eA9 = ex2(cLA * t89.y);
                float eB0 = ex2(cLB * t01.x), eB1 = ex2(cLB * t01.y);
                float eB8 = ex2(cLB * t89.x), eB9 = ex2(cLB * t89.y);
                zA += (eA0 + eA1) + (eA8 + eA9);
                zB += (eB0 + eB1) + (eB8 + eB9);
                unsigned iA = uA + (unsigned)mb, iB = uB + (unsigned)mb;
                float vA0 = keep_or_zero(iA, eA0),     vA1 = keep_or_zero(iA + 1, eA1);
                float vA8 = keep_or_zero(iA + 8, eA8), vA9 = keep_or_zero(iA + 9, eA9);
                float vB0 = keep_or_zero(iB, eB0),     vB1 = keep_or_zero(iB + 1, eB1);
                float vB8 = keep_or_zero(iB + 8, eB8), vB9 = keep_or_zero(iB + 9, eB9);
                ahi[s][0] = pack_h2(vA0, vA1);
                ahi[s][1] = pack_h2(vB0, vB1);
                ahi[s][2] = pack_h2(vA8, vA9);
                ahi[s][3] = pack_h2(vB8, vB9);
            }
#pragma unroll
            for (int nt = 0; nt < 16; ++nt) {
                int boff = (nt * 8 + qr) * SROW + ms2 * 16 + qa * 4;
                uint4 bh = *(const uint4*)&VhS[boff];
                mma16816(acc[nt], ahi[0][0], ahi[0][1], ahi[0][2], ahi[0][3], bh.x, bh.y);
                mma16816(acc[nt], ahi[1][0], ahi[1][1], ahi[1][2], ahi[1][3], bh.z, bh.w);
            }
        }

        if (c < 15) { CP_WAIT0(); __syncthreads(); }
    }

    // Z quad reduction (lanes 4r..4r+3 share d)
    zA += __shfl_xor_sync(0xffffffffu, zA, 1);
    zA += __shfl_xor_sync(0xffffffffu, zA, 2);
    zB += __shfl_xor_sync(0xffffffffu, zB, 1);
    zB += __shfl_xor_sync(0xffffffffu, zB, 2);
    float izA = 1.0f / (0.6f * zA);
    float izB = 1.0f / (0.6f * zB);

    float* obA = out + ((long)n << 14) + (long)dA * 128 + qa * 2;
    float* obB = out + ((long)n << 14) + (long)dB * 128 + qa * 2;
#pragma unroll
    for (int nt = 0; nt < 16; ++nt) {
        *(float2*)&obA[nt * 8] = make_float2(acc[nt][0] * izA, acc[nt][1] * izA);
        *(float2*)&obB[nt * 8] = make_float2(acc[nt][2] * izB, acc[nt][3] * izB);
    }
}

// ---------------------------------------------------------------------------
extern "C" void kernel_launch(void* const* d_in, const int* in_sizes, int n_in,
                              void* d_out, int out_size) {
    const float* x1 = (const float*)d_in[0];
    const float* x2 = (const float*)d_in[1];
    const float* x3 = (const float*)d_in[2];
    const float* x4 = (const float*)d_in[3];
    const float* W  = (const float*)d_in[4];
    const float* b  = (const float*)d_in[5];
    float* out = (float*)d_out;

    cudaFuncSetAttribute(lin_kernel,  cudaFuncAttributeMaxDynamicSharedMemorySize, LIN_SMEM);
    cudaFuncSetAttribute(main_kernel, cudaFuncAttributeMaxDynamicSharedMemorySize, SMEM_BYTES);

    lin_kernel<<<64, 256, LIN_SMEM>>>(x1, x2, x3, x4, W, b);  // launch 1
    mid_kernel<<<512, 256>>>();                               // launch 2
    main_kernel<<<1024, 256, SMEM_BYTES>>>(out);              // launch 3
}

// round 12
// speedup vs baseline: 1.2010x; 1.0554x over previous
#include <cuda_runtime.h>
#include <cuda_bf16.h>
#include <cuda_fp16.h>
#include <stdint.h>

// ---------------- scratch (__device__ globals; no allocations) ----------------
__device__ float    g_L[4096 * 128];      // q | k | v | scale rows
__device__ float    g_c[1024 * 128];      // Z_d * exp(M_d - s[n][d])
__device__ float    g_qk[1024 * 1024];
__device__ unsigned g_Menc[1024];         // row max of qk, order-encoded uint
// V^T fp16 pairs, frag-order permuted: g_Bh[k*512 + u(P)], P = m/2 pair index
__device__ uint32_t g_Bh[128 * 512];

__device__ __forceinline__ float ex2(float x) {
    float y; asm("ex2.approx.ftz.f32 %0, %1;" : "=f"(y) : "f"(x)); return y;
}
__device__ __forceinline__ uint32_t smem_u32(const void* p) {
    uint32_t a;
    asm("{ .reg .u64 t; cvta.to.shared.u64 t, %1; cvt.u32.u64 %0, t; }" : "=r"(a) : "l"(p));
    return a;
}
__device__ __forceinline__ uint32_t pack_h2(float a, float b) {
    __half2 h = __floats2half2_rn(a, b);
    return *(uint32_t*)&h;
}
__device__ __forceinline__ float2 h2f2(uint32_t u) {
    __half2 h = *(__half2*)&u;
    return __half22float2(h);
}
// order-preserving float<->uint (for atomicMax row-max)
__device__ __forceinline__ unsigned enc_f(float f) {
    unsigned u = __float_as_uint(f);
    return (u & 0x80000000u) ? ~u : (u | 0x80000000u);
}
__device__ __forceinline__ float dec_f(unsigned k) {
    return __uint_as_float((k & 0x80000000u) ? (k ^ 0x80000000u) : ~k);
}

// ---- JAX threefry2x32 (partitionable): key=(0,42), ctr=(0,i), out = o0^o1 ----
__device__ __forceinline__ unsigned int jax_threefry_bits(unsigned int idx) {
    const unsigned int K1 = 42u;
    const unsigned int K2 = 42u ^ 0x1BD11BDAu;
    unsigned int x0 = 0u;
    unsigned int x1 = idx + K1;
#define TFR(r) { x0 += x1; x1 = __funnelshift_l(x1, x1, (r)); x1 ^= x0; }
    TFR(13) TFR(15) TFR(26) TFR(6)   x0 += K1; x1 += K2 + 1u;
    TFR(17) TFR(29) TFR(16) TFR(24)  x0 += K2; x1 += 0u + 2u;
    TFR(13) TFR(15) TFR(26) TFR(6)   x0 += 0u; x1 += K1 + 3u;
    TFR(17) TFR(29) TFR(16) TFR(24)  x0 += K1; x1 += K2 + 4u;
    TFR(13) TFR(15) TFR(26) TFR(6)   x0 += K2; x1 += 0u + 5u;
#undef TFR
    return x0 ^ x1;
}
// keep ⟺ (bits>>9) < 5033165 ⟺ bits < 5033165*512  (uniform<0.6 exact)
__device__ __forceinline__ float keep_or_zero(unsigned idx, float e) {
    return (jax_threefry_bits(idx) < 2576980480u) ? e : 0.f;
}

__device__ __forceinline__ void mma16816(float* d,
    uint32_t a0, uint32_t a1, uint32_t a2, uint32_t a3, uint32_t b0, uint32_t b1) {
    asm volatile("mma.sync.aligned.m16n8k16.row.col.f32.f16.f16.f32 "
        "{%0,%1,%2,%3}, {%4,%5,%6,%7}, {%8,%9}, {%0,%1,%2,%3};"
        : "+f"(d[0]), "+f"(d[1]), "+f"(d[2]), "+f"(d[3])
        : "r"(a0), "r"(a1), "r"(a2), "r"(a3), "r"(b0), "r"(b1));
}

#define CP_ASYNC16(dst, src) \
    asm volatile("cp.async.cg.shared.global [%0], [%1], 16;" :: "r"(dst), "l"(src) : "memory")
#define CP_COMMIT() asm volatile("cp.async.commit_group;" ::: "memory")
#define CP_WAIT0()  asm volatile("cp.async.wait_group 0;" ::: "memory")

// ---------------- 1) lin via tensor cores, exact hi/lo split -----------------
// C[4096,128] = X @ W^T + b.  Block: 32 rows x 64 cols; 256 blocks.
// Register-prefetch pipeline across 8 k-chunks of 64.
#define LROW 36

__global__ void __launch_bounds__(256)
lin_kernel(const float* __restrict__ x1, const float* __restrict__ x2,
           const float* __restrict__ x3, const float* __restrict__ x4,
           const float* __restrict__ W, const float* __restrict__ b) {
    __shared__ uint32_t lsm[192 * LROW];          // 27648 B
    uint32_t* Xh = lsm;
    uint32_t* Xl = lsm + 32 * LROW;
    uint32_t* Wh = lsm + 64 * LROW;
    uint32_t* Wl = lsm + 128 * LROW;

    int t = threadIdx.x, w = t >> 5, lane = t & 31;
    int rb = blockIdx.x;                 // 256 blocks
    int rbr = rb >> 1;                   // row-block 0..127 (32 rows each)
    int jb = (rb & 1) << 6;              // j half: 0 or 64
    int r0 = rbr * 32;
    if (t < 4) g_Menc[rb * 4 + t] = 0u;  // -inf encoding (1024 over 256 blocks)

    const float* srcs[4] = {x1, x2, x3, x4};
    const float* xsrc = srcs[rbr >> 5];
    int rloc = r0 & 1023;

    int qa = lane & 3, qr = lane >> 2;
    int rt0 = (w & 1) << 4;              // 16-row tile
    int jq  = (w >> 1) << 4;             // 16-col group
    float acc[2][4];
#pragma unroll
    for (int i = 0; i < 2; ++i)
#pragma unroll
        for (int j = 0; j < 4; ++j) acc[i][j] = 0.f;

    // prefetch chunk 0
    float4 px[2], pw[4];
#pragma unroll
    for (int i = 0; i < 2; ++i) {
        int fl = t + i * 256;
        px[i] = *(const float4*)&xsrc[(rloc + (fl >> 4)) * 512 + (fl & 15) * 4];
    }
#pragma unroll
    for (int i = 0; i < 4; ++i) {
        int fl = t + i * 256;
        pw[i] = *(const float4*)&W[(jb + (fl >> 4)) * 512 + (fl & 15) * 4];
    }

#pragma unroll 1
    for (int c = 0; c < 8; ++c) {
        __syncthreads();                 // prior compute done reading smem
        // store+convert prefetched chunk
#pragma unroll
        for (int i = 0; i < 2; ++i) {
            int fl = t + i * 256;
            float4 v = px[i];
            uint32_t h0 = pack_h2(v.x, v.y), h1 = pack_h2(v.z, v.w);
            float2 f0 = h2f2(h0), f1 = h2f2(h1);
            int o = (fl >> 4) * LROW + (fl & 15) * 2;
            Xh[o] = h0; Xh[o + 1] = h1;
            Xl[o]     = pack_h2(v.x - f0.x, v.y - f0.y);
            Xl[o + 1] = pack_h2(v.z - f1.x, v.w - f1.y);
        }
#pragma unroll
        for (int i = 0; i < 4; ++i) {
            int fl = t + i * 256;
            float4 v = pw[i];
            uint32_t h0 = pack_h2(v.x, v.y), h1 = pack_h2(v.z, v.w);
            float2 f0 = h2f2(h0), f1 = h2f2(h1);
            int o = (fl >> 4) * LROW + (fl & 15) * 2;
            Wh[o] = h0; Wh[o + 1] = h1;
            Wl[o]     = pack_h2(v.x - f0.x, v.y - f0.y);
            Wl[o + 1] = pack_h2(v.z - f1.x, v.w - f1.y);
        }
        __syncthreads();

        // issue next chunk's loads early (latency hides under mma below)
        if (c < 7) {
            int cn = (c + 1) * 64;
#pragma unroll
            for (int i = 0; i < 2; ++i) {
                int fl = t + i * 256;
                px[i] = *(const float4*)&xsrc[(rloc + (fl >> 4)) * 512 + cn + (fl & 15) * 4];
            }
#pragma unroll
            for (int i = 0; i < 4; ++i) {
                int fl = t + i * 256;
                pw[i] = *(const float4*)&W[(jb + (fl >> 4)) * 512 + cn + (fl & 15) * 4];
            }
        }

#pragma unroll
        for (int ks = 0; ks < 4; ++ks) {
            int kp = ks * 8 + qa;
            int ra = (rt0 + qr) * LROW, ra8 = (rt0 + qr + 8) * LROW;
            uint32_t ah0 = Xh[ra + kp],     ah1 = Xh[ra8 + kp];
            uint32_t ah2 = Xh[ra + kp + 4], ah3 = Xh[ra8 + kp + 4];
            uint32_t al0 = Xl[ra + kp],     al1 = Xl[ra8 + kp];
            uint32_t al2 = Xl[ra + kp + 4], al3 = Xl[ra8 + kp + 4];
#pragma unroll
            for (int jt = 0; jt < 2; ++jt) {
                int jr = (jq + jt * 8 + qr) * LROW;
                uint32_t bh0 = Wh[jr + kp], bh1 = Wh[jr + kp + 4];
                uint32_t bl0 = Wl[jr + kp], bl1 = Wl[jr + kp + 4];
                mma16816(acc[jt], ah0, ah1, ah2, ah3, bh0, bh1);
                mma16816(acc[jt], ah0, ah1, ah2, ah3, bl0, bl1);
                mma16816(acc[jt], al0, al1, al2, al3, bh0, bh1);
            }
        }
    }

    // epilogue: + bias, write g_L
    int row0 = r0 + rt0 + qr;
#pragma unroll
    for (int jt = 0; jt < 2; ++jt) {
        int col = jb + jq + jt * 8 + qa * 2;
        float2 bb = *(const float2*)&b[col];
        *(float2*)&g_L[row0 * 128 + col] =
            make_float2(acc[jt][0] + bb.x, acc[jt][1] + bb.y);
        *(float2*)&g_L[(row0 + 8) * 128 + col] =
            make_float2(acc[jt][2] + bb.x, acc[jt][3] + bb.y);
    }
}

// ---------------- 2) fused mid: qk (0-255) | csm (256-383) | vsplit (384-511) -
__global__ void mid_kernel() {
    __shared__ float sA[64][64];
    __shared__ float sB[64][64];
    int t = threadIdx.x;                 // 256
    int bxAll = blockIdx.x;

    if (bxAll < 256) {
        // ---- qk = q @ k^T tile + fused row-max ----
        const float* q = g_L;
        const float* kmat = g_L + 1024 * 128;
        int bx = bxAll & 15, by = bxAll >> 4;
        int tr = (t >> 4) << 2, tc = (t & 15) << 2;
        float acc[4][4] = {};
        for (int k0 = 0; k0 < 128; k0 += 64) {
            __syncthreads();
#pragma unroll
            for (int i = 0; i < 4; ++i) {
                int fl4 = t + i * 256;
                int r = fl4 >> 4, kg = fl4 & 15;
                float4 va = *(const float4*)&q[(by * 64 + r) * 128 + k0 + kg * 4];
                sA[kg * 4 + 0][r] = va.x; sA[kg * 4 + 1][r] = va.y;
                sA[kg * 4 + 2][r] = va.z; sA[kg * 4 + 3][r] = va.w;
                float4 vb = *(const float4*)&kmat[(bx * 64 + r) * 128 + k0 + kg * 4];
                sB[kg * 4 + 0][r] = vb.x; sB[kg * 4 + 1][r] = vb.y;
                sB[kg * 4 + 2][r] = vb.z; sB[kg * 4 + 3][r] = vb.w;
            }
            __syncthreads();
#pragma unroll 8
            for (int kx = 0; kx < 64; ++kx) {
                float a[4], bv[4];
                *(float4*)a  = *(const float4*)&sA[kx][tr];
                *(float4*)bv = *(const float4*)&sB[kx][tc];
#pragma unroll
                for (int i = 0; i < 4; ++i)
#pragma unroll
                    for (int j = 0; j < 4; ++j) acc[i][j] += a[i] * bv[j];
            }
        }
#pragma unroll
        for (int i = 0; i < 4; ++i) {
            *(float4*)&g_qk[(by * 64 + tr + i) * 1024 + bx * 64 + tc] =
                make_float4(acc[i][0], acc[i][1], acc[i][2], acc[i][3]);
            float m = fmaxf(fmaxf(acc[i][0], acc[i][1]), fmaxf(acc[i][2], acc[i][3]));
            atomicMax(&g_Menc[by * 64 + tr + i], enc_f(m));
        }
    } else if (bxAll < 384) {
        // ---- column softmax -> c ----
        float* red = &sA[0][0];
        int d = bxAll - 256;
        const float* S = g_L + 3072 * 128;
        float mx = -1e30f;
        for (int n = t; n < 1024; n += 256) mx = fmaxf(mx, S[n * 128 + d]);
        red[t] = mx; __syncthreads();
        for (int s = 128; s >= 1; s >>= 1) { if (t < s) red[t] = fmaxf(red[t], red[t + s]); __syncthreads(); }
        float Md = red[0]; __syncthreads();
        float z = 0.f;
        for (int n = t; n < 1024; n += 256) z += __expf(S[n * 128 + d] - Md);
        red[t] = z; __syncthreads();
        for (int s = 128; s >= 1; s >>= 1) { if (t < s) red[t] += red[t + s]; __syncthreads(); }
        float Zd = red[0]; __syncthreads();
        for (int n = t; n < 1024; n += 256) g_c[n * 128 + d] = Zd * __expf(Md - S[n * 128 + d]);
    } else {
        // ---- V transpose + fp16 pack, frag-order permute ----
        float (*tile)[64] = sA;
        const float* V = g_L + 2048 * 128;
        int bid = bxAll - 384;
        int mt = bid & 31, kt = bid >> 5;
#pragma unroll
        for (int i = 0; i < 4; ++i) {
            int fl = t + i * 256;
            int mi = fl >> 5, kj = fl & 31;
            tile[mi][kj] = V[(mt * 32 + mi) * 128 + kt * 32 + kj];
        }
        __syncthreads();
#pragma unroll
        for (int i = 0; i < 2; ++i) {
            int fl = t + i * 256;            // 0..511
            int ki = fl >> 4, mj = fl & 15;
            float v0 = tile[2 * mj][ki], v1 = tile[2 * mj + 1][ki];
            int k = kt * 32 + ki;
            int P = mt * 16 + mj;            // global pair index (m/2)
            int u = (P & ~31) + (P & 16) + ((P & 3) << 2) + ((P >> 2) & 3);
            g_Bh[k * 512 + u] = pack_h2(v0, v1);
        }
    }
}

// ---------------- 3) main: in-register E frags (fp16) x V_hi  (R6 exact) -----
// smem: qkrow(4096) | cvals(512) | Vbuf0(24576) | Vbuf1(24576) = 53760B
#define SM_QK   0
#define SM_CV   4096
#define SM_V0   4608
#define SM_V1   (4608 + 24576)
#define SMEM_BYTES (4608 + 2 * 24576)
#define SROW 48   // uint32 row stride (192B): conflict-free LDS.128

__global__ void __launch_bounds__(256, 2)
main_kernel(float* __restrict__ out) {
    extern __shared__ char smem[];
    float* qkrow = (float*)(smem + SM_QK);
    float* cvals = (float*)(smem + SM_CV);
    uint32_t sbase = smem_u32(smem);

    int t = threadIdx.x, w = t >> 5, lane = t & 31;
    int n = blockIdx.x;
    float Mn = dec_f(g_Menc[n]);
    const float4* gBh4 = (const float4*)g_Bh;

    // stage chunk 0 into buf0 via cp.async
    {
#pragma unroll
        for (int i = 0; i < 4; ++i) {
            int fl = t + i * 256;
            int row = fl >> 3, idx = fl & 7;
            CP_ASYNC16(sbase + SM_V0 + (uint32_t)(row * SROW + idx * 4) * 4,
                       gBh4 + row * 128 + idx);
        }
        CP_COMMIT();
    }

    // qk row (pre-subtract Mn) and cvals (pre-mul log2e)
    {
        float4 v = *(const float4*)&g_qk[n * 1024 + t * 4];
        v.x -= Mn; v.y -= Mn; v.z -= Mn; v.w -= Mn;
        *(float4*)&qkrow[t * 4] = v;
        if (t < 128) cvals[t] = g_c[n * 128 + t] * 1.4426950408889634f;
    }
    CP_WAIT0();
    __syncthreads();

    int qa = lane & 3;                 // quad pos -> m pair
    int qr = lane >> 2;                // quad id  -> d row / b col
    int dA = w * 16 + qr, dB = dA + 8;
    float cLA = cvals[dA], cLB = cvals[dB];
    unsigned uA = ((unsigned)n << 17) + ((unsigned)dA << 10);
    unsigned uB = ((unsigned)n << 17) + ((unsigned)dB << 10);

    float acc[16][4];
#pragma unroll
    for (int i = 0; i < 16; ++i)
#pragma unroll
        for (int j = 0; j < 4; ++j) acc[i][j] = 0.f;
    float zA = 0.f, zB = 0.f;

#pragma unroll 1
    for (int c = 0; c < 16; ++c) {
        const uint32_t* VhS = (const uint32_t*)(smem + ((c & 1) ? SM_V1 : SM_V0));

        // prefetch next chunk into other buffer
        if (c < 15) {
            uint32_t dstb = sbase + ((c & 1) ? SM_V0 : SM_V1);
#pragma unroll
            for (int i = 0; i < 4; ++i) {
                int fl = t + i * 256;
                int row = fl >> 3, idx = fl & 7;
                CP_ASYNC16(dstb + (uint32_t)(row * SROW + idx * 4) * 4,
                           gBh4 + row * 128 + (c + 1) * 8 + idx);
            }
            CP_COMMIT();
        }

#pragma unroll 1
        for (int ms2 = 0; ms2 < 2; ++ms2) {
            int m0 = c * 64 + ms2 * 32;
            uint32_t ahi[2][4];
#pragma unroll
            for (int s = 0; s < 2; ++s) {
                int mb = m0 + s * 16 + qa * 2;
                float2 t01 = *(const float2*)&qkrow[mb];
                float2 t89 = *(const float2*)&qkrow[mb + 8];
                float eA0 = ex2(cLA * t01.x), eA1 = ex2(cLA * t01.y);
                float eA8 = ex2(cLA * t89.x), eA9 = ex2(cLA * t89.y);
                float eB0 = ex2(cLB * t01.x), eB1 = ex2(cLB * t01.y);
                float eB8 = ex2(cLB * t89.x), eB9 = ex2(cLB * t89.y);
                zA += (eA0 + eA1) + (eA8 + eA9);
                zB += (eB0 + eB1) + (eB8 + eB9);
                unsigned iA = uA + (unsigned)mb, iB = uB + (unsigned)mb;
                float vA0 = keep_or_zero(iA, eA0),     vA1 = keep_or_zero(iA + 1, eA1);
                float vA8 = keep_or_zero(iA + 8, eA8), vA9 = keep_or_zero(iA + 9, eA9);
                float vB0 = keep_or_zero(iB, eB0),     vB1 = keep_or_zero(iB + 1, eB1);
                float vB8 = keep_or_zero(iB + 8, eB8), vB9 = keep_or_zero(iB + 9, eB9);
                ahi[s][0] = pack_h2(vA0, vA1);
                ahi[s][1] = pack_h2(vB0, vB1);
                ahi[s][2] = pack_h2(vA8, vA9);
                ahi[s][3] = pack_h2(vB8, vB9);
            }
#pragma unroll
            for (int nt = 0; nt < 16; ++nt) {
                int boff = (nt * 8 + qr) * SROW + ms2 * 16 + qa * 4;
                uint4 bh = *(const uint4*)&VhS[boff];
                mma16816(acc[nt], ahi[0][0], ahi[0][1], ahi[0][2], ahi[0][3], bh.x, bh.y);
                mma16816(acc[nt], ahi[1][0], ahi[1][1], ahi[1][2], ahi[1][3], bh.z, bh.w);
            }
        }

        if (c < 15) { CP_WAIT0(); __syncthreads(); }
    }

    // Z quad reduction (lanes 4r..4r+3 share d)
    zA += __shfl_xor_sync(0xffffffffu, zA, 1);
    zA += __shfl_xor_sync(0xffffffffu, zA, 2);
    zB += __shfl_xor_sync(0xffffffffu, zB, 1);
    zB += __shfl_xor_sync(0xffffffffu, zB, 2);
    float izA = 1.0f / (0.6f * zA);
    float izB = 1.0f / (0.6f * zB);

    float* obA = out + ((long)n << 14) + (long)dA * 128 + qa * 2;
    float* obB = out + ((long)n << 14) + (long)dB * 128 + qa * 2;
#pragma unroll
    for (int nt = 0; nt < 16; ++nt) {
        *(float2*)&obA[nt * 8] = make_float2(acc[nt][0] * izA, acc[nt][1] * izA);
        *(float2*)&obB[nt * 8] = make_float2(acc[nt][2] * izB, acc[nt][3] * izB);
    }
}

// ---------------------------------------------------------------------------
extern "C" void kernel_launch(void* const* d_in, const int* in_sizes, int n_in,
                              void* d_out, int out_size) {
    const float* x1 = (const float*)d_in[0];
    const float* x2 = (const float*)d_in[1];
    const float* x3 = (const float*)d_in[2];
    const float* x4 = (const float*)d_in[3];
    const float* W  = (const float*)d_in[4];
    const float* b  = (const float*)d_in[5];
    float* out = (float*)d_out;

    cudaFuncSetAttribute(main_kernel, cudaFuncAttributeMaxDynamicSharedMemorySize, SMEM_BYTES);

    lin_kernel<<<256, 256>>>(x1, x2, x3, x4, W, b);   // launch 1
    mid_kernel<<<512, 256>>>();                       // launch 2
    main_kernel<<<1024, 256, SMEM_BYTES>>>(out);      // launch 3
}